// round 8
// baseline (speedup 1.0000x reference)
#include <cuda_runtime.h>
#include <cstdint>

// HONU order-2: out[i] = sum_{j<=k} W[p(j,k)] x[i,j] x[i,k] + b
// Round 8: A (zero-filled 64x64) lives in __constant__ memory -> operand
// broadcast rides the uniform constant port instead of the smem crossbar
// (R5/R7 proved LDS wavefronts = architectural bytes; broadcast pays 32x).
// Warp-pair per 32 rows: warp parity p owns j = 2m+p (warp-uniform LDC).
// x row in 32 f32x2 register packs; triangular packed-FMA inner products.

__device__   __align__(16) float      A_g[64 * 64];
__constant__ __align__(16) ulonglong2 A_c[64 * 16];   // 16 KB

__global__ void expand_kernel(const float* __restrict__ W) {
    int i = blockIdx.x * 256 + threadIdx.x;            // 4096 elements
    if (i < 64 * 64) {
        int j = i >> 6, k = i & 63;
        float v = 0.0f;
        if (k >= j) v = W[j * 64 - ((j * (j - 1)) >> 1) + (k - j)];
        A_g[i] = v;
    }
}

__device__ __forceinline__ void fma2(uint64_t& d, uint64_t a, uint64_t b) {
    asm("fma.rn.f32x2 %0, %1, %2, %0;" : "+l"(d) : "l"(a), "l"(b));
}
__device__ __forceinline__ uint64_t add2(uint64_t a, uint64_t b) {
    uint64_t d;
    asm("add.rn.f32x2 %0, %1, %2;" : "=l"(d) : "l"(a), "l"(b));
    return d;
}

__global__ void __launch_bounds__(256) honu_kernel(
    const float* __restrict__ x, const float* __restrict__ bias,
    float* __restrict__ out)
{
    __shared__ float part[128];
    const int tid  = threadIdx.x;
    const int wid  = tid >> 5;
    const int lane = tid & 31;
    const int p    = wid & 1;                    // j-parity (warp-uniform)
    const int rloc = (wid >> 1) * 32 + lane;     // local row 0..127
    const int row  = blockIdx.x * 128 + rloc;

    // --- x row -> 32 f32x2 packs in registers (16 LDG.128)
    uint64_t xp[32];
    const uint4* xg = reinterpret_cast<const uint4*>(x + (size_t)row * 64);
    #pragma unroll
    for (int i = 0; i < 16; ++i) {
        uint4 v = __ldg(xg + i);
        asm("mov.b64 %0, {%1,%2};" : "=l"(xp[2 * i])     : "r"(v.x), "r"(v.y));
        asm("mov.b64 %0, {%1,%2};" : "=l"(xp[2 * i + 1]) : "r"(v.z), "r"(v.w));
    }

    // --- Triangular inner products: j = 2m+p, packs q >= m>>1 (zero-fill
    //     below the diagonal makes the even rounding safe).
    const int sh = p * 32;
    float acc = 0.0f;
    #pragma unroll
    for (int m = 0; m < 32; ++m) {
        const int j = 2 * m + p;
        uint64_t c0 = 0, c1 = 0;
        #pragma unroll
        for (int q = (m >> 1); q < 16; ++q) {
            ulonglong2 a = A_c[j * 16 + q];      // uniform LDC.128
            fma2(c0, a.x, xp[2 * q]);
            fma2(c1, a.y, xp[2 * q + 1]);
        }
        uint64_t c = add2(c0, c1);
        uint32_t lo, hi;
        asm("mov.b64 {%0,%1}, %2;" : "=r"(lo), "=r"(hi) : "l"(c));
        float inner = __uint_as_float(lo) + __uint_as_float(hi);
        float xj = __uint_as_float((uint32_t)(xp[m] >> sh));
        acc = fmaf(xj, inner, acc);
    }

    // --- Combine the two parity warps of each row group via smem
    if (p == 1) part[rloc] = acc;
    __syncthreads();
    if (p == 0) out[row] = acc + part[rloc] + __ldg(bias);
}

extern "C" void kernel_launch(void* const* d_in, const int* in_sizes, int n_in,
                              void* d_out, int out_size) {
    const float* x = (const float*)d_in[0];   // (16384, 64) f32
    const float* W = (const float*)d_in[1];   // (2145,)  f32 (first 2080 used)
    const float* b = (const float*)d_in[2];   // (1,)     f32
    float*     out = (float*)d_out;           // (16384,) f32

    expand_kernel<<<16, 256>>>(W);

    void* Ag_ptr = nullptr;
    cudaGetSymbolAddress(&Ag_ptr, A_g);
    cudaMemcpyToSymbolAsync(A_c, Ag_ptr, 64 * 64 * sizeof(float), 0,
                            cudaMemcpyDeviceToDevice, 0);

    const int blocks = out_size / 128;        // 128 CTAs x 256 threads
    honu_kernel<<<blocks, 256>>>(x, b, out);
}

// round 9
// speedup vs baseline: 1.4742x; 1.4742x over previous
#include <cuda_runtime.h>
#include <cstdint>

// HONU order-2: out[i] = sum_{j<=k} W[p(j,k)] x[i,j] x[i,k] + b
// Round 9: A (zero-filled 64x64) in GLOBAL memory, read with warp-uniform
// __ldg (L1-resident; 1 wavefront/load vs 4 on the smem crossbar).
// Warp parity p owns j = 4m+p (uniform); x row lives in 32 f32x2 register
// packs; main loop fully specialized on p (template) so every index is
// compile-time. Triangular chunks c = m..15. 256 CTAs x 256 thr, 2048 warps.

__device__ __align__(16) float A_g[64 * 64];

__global__ void expand_kernel(const float* __restrict__ W) {
    int i = blockIdx.x * 256 + threadIdx.x;            // 4096 elements
    if (i < 64 * 64) {
        int j = i >> 6, k = i & 63;
        float v = 0.0f;
        if (k >= j) v = W[j * 64 - ((j * (j - 1)) >> 1) + (k - j)];
        A_g[i] = v;
    }
}

__device__ __forceinline__ void fma2(uint64_t& d, uint64_t a, uint64_t b) {
    asm("fma.rn.f32x2 %0, %1, %2, %0;" : "+l"(d) : "l"(a), "l"(b));
}
__device__ __forceinline__ uint64_t add2(uint64_t a, uint64_t b) {
    uint64_t d;
    asm("add.rn.f32x2 %0, %1, %2;" : "=l"(d) : "l"(a), "l"(b));
    return d;
}
__device__ __forceinline__ uint64_t pack2(uint32_t lo, uint32_t hi) {
    uint64_t d;
    asm("mov.b64 %0, {%1,%2};" : "=l"(d) : "r"(lo), "r"(hi));
    return d;
}

template <int P>
__device__ __forceinline__ float mainloop(const uint64_t* __restrict__ xp) {
    const uint4* A4 = reinterpret_cast<const uint4*>(A_g);
    float acc = 0.0f;
    #pragma unroll
    for (int m = 0; m < 16; ++m) {
        const int j = 4 * m + P;
        uint64_t c0 = 0, c1 = 0;
        #pragma unroll
        for (int c = m; c < 16; ++c) {
            uint4 av = __ldg(A4 + j * 16 + c);     // warp-uniform LDG.128
            fma2(c0, pack2(av.x, av.y), xp[2 * c]);
            fma2(c1, pack2(av.z, av.w), xp[2 * c + 1]);
        }
        uint64_t cc = add2(c0, c1);
        uint32_t lo, hi;
        asm("mov.b64 {%0,%1}, %2;" : "=r"(lo), "=r"(hi) : "l"(cc));
        float inner = __uint_as_float(lo) + __uint_as_float(hi);
        // x_j from register pack: pack index 2m + P/2, half P&1 (compile-time)
        uint64_t xpk = xp[2 * m + (P >> 1)];
        uint32_t xb;
        if (P & 1) asm("mov.b64 {_,%0}, %1;" : "=r"(xb) : "l"(xpk));
        else       asm("mov.b64 {%0,_}, %1;" : "=r"(xb) : "l"(xpk));
        acc = fmaf(__uint_as_float(xb), inner, acc);
    }
    return acc;
}

#define AST 68   // xs stride in floats

__global__ void __launch_bounds__(256, 2) honu_kernel(
    const float* __restrict__ x, const float* __restrict__ bias,
    float* __restrict__ out)
{
    __shared__ __align__(16) float xs[64 * AST];   // 17.4 KB
    __shared__ float part[3][64];

    const int tid  = threadIdx.x;
    const int wid  = tid >> 5;
    const int lane = tid & 31;
    const int p    = wid & 3;                      // j-parity (warp-uniform)
    const int rl   = (wid >> 2) * 32 + lane;       // local row 0..63
    const int row  = blockIdx.x * 64 + rl;

    // --- Stage 64x64 x tile, coalesced float4 -> stride-17-float4 smem
    {
        const float4* xg4 = reinterpret_cast<const float4*>(x + (size_t)blockIdx.x * 64 * 64);
        float4*       xs4 = reinterpret_cast<float4*>(xs);
        #pragma unroll
        for (int it = 0; it < 4; ++it) {
            int i = it * 256 + tid;                // 0..1023
            int r = i >> 4, c = i & 15;
            xs4[r * 17 + c] = xg4[i];
        }
    }
    __syncthreads();

    // --- x row -> 32 f32x2 packs (16 x ld.shared.v2.b64, 16B-aligned)
    uint64_t xp[32];
    {
        const unsigned xb = (unsigned)__cvta_generic_to_shared(xs) + rl * (AST * 4);
        #pragma unroll
        for (int q = 0; q < 16; ++q)
            asm volatile("ld.shared.v2.b64 {%0,%1}, [%2];"
                         : "=l"(xp[2 * q]), "=l"(xp[2 * q + 1]) : "r"(xb + q * 16));
    }

    float acc;
    if      (p == 0) acc = mainloop<0>(xp);
    else if (p == 1) acc = mainloop<1>(xp);
    else if (p == 2) acc = mainloop<2>(xp);
    else             acc = mainloop<3>(xp);

    // --- Combine the 4 parity partials per row
    if (p) part[p - 1][rl] = acc;
    __syncthreads();
    if (p == 0)
        out[row] = acc + part[0][rl] + part[1][rl] + part[2][rl] + __ldg(bias);
}

extern "C" void kernel_launch(void* const* d_in, const int* in_sizes, int n_in,
                              void* d_out, int out_size) {
    const float* x = (const float*)d_in[0];   // (16384, 64) f32
    const float* W = (const float*)d_in[1];   // (2145,)  f32 (first 2080 used)
    const float* b = (const float*)d_in[2];   // (1,)     f32
    float*     out = (float*)d_out;           // (16384,) f32

    expand_kernel<<<16, 256>>>(W);

    const int blocks = out_size / 64;         // 256 CTAs x 256 threads
    honu_kernel<<<blocks, 256>>>(x, b, out);
}

// round 10
// speedup vs baseline: 1.7857x; 1.2113x over previous
#include <cuda_runtime.h>
#include <cstdint>

// HONU order-2 as triangular register-blocked GEMM:
//   U[j][n] = W[p(j,n)] (n>=j) else 0;  Y = X U;  out = rowsum(Y .* X) + b
// Warp = 32 rows x column-pair {4c..4c+3, 60-4c..63-4c}, c = warp id:
// block A trips 4c+4, block B trips 64-4c -> constant 68 per warp (balanced
// triangularity, warp-uniform, no divergence). Per iter: 1 scalar x LDS
// (1 wavefront) + 1 uniform 16B U LDS (1 wavefront) + 2 FFMA2.
// 512 CTAs x 256 threads = 4096 warps (43% occ). Single kernel.

#define THREADS 256
#define XT 33                    // xs_T row stride (floats)

__device__ __forceinline__ void lds_v2u64(uint64_t& a, uint64_t& b, unsigned addr) {
    asm volatile("ld.shared.v2.b64 {%0,%1}, [%2];" : "=l"(a), "=l"(b) : "r"(addr));
}
__device__ __forceinline__ void fma2(uint64_t& d, uint64_t a, uint64_t b) {
    asm("fma.rn.f32x2 %0, %1, %2, %0;" : "+l"(d) : "l"(a), "l"(b));
}
__device__ __forceinline__ float lds32(unsigned addr) {
    float v;
    asm volatile("ld.shared.f32 %0, [%1];" : "=f"(v) : "r"(addr));
    return v;
}
__device__ __forceinline__ uint64_t splat(float x) {
    uint64_t d;
    asm("mov.b64 %0, {%1,%1};" : "=l"(d) : "r"(__float_as_uint(x)));
    return d;
}

__global__ void __launch_bounds__(THREADS) honu_kernel(
    const float* __restrict__ x, const float* __restrict__ W,
    const float* __restrict__ bias, float* __restrict__ out)
{
    __shared__ __align__(16) float U_s[64 * 64];     // 16 KB zero-filled square
    __shared__ float xs_T[64 * XT];                  // 8.25 KB transposed x tile
    __shared__ float part[8][32];

    const int tid  = threadIdx.x;
    const int wid  = tid >> 5;                       // column-pair c (uniform)
    const int lane = tid & 31;                       // row within tile
    const int row0 = blockIdx.x * 32;

    // --- Expand U from packed W (16 elements/thread; W is L2-resident)
    #pragma unroll
    for (int it = 0; it < 16; ++it) {
        int e = it * THREADS + tid;                  // 0..4095
        int j = e >> 6, n = e & 63;
        float v = 0.0f;
        if (n >= j) v = __ldg(&W[j * 64 - ((j * (j - 1)) >> 1) + (n - j)]);
        U_s[e] = v;
    }
    // --- Stage x tile transposed: xs_T[k][r] = x[row0+r][k]
    {
        const float4* xg4 = reinterpret_cast<const float4*>(x + (size_t)row0 * 64);
        #pragma unroll
        for (int it = 0; it < 2; ++it) {
            int i = it * THREADS + tid;              // 0..511 float4s
            int r = i >> 4, c4 = i & 15;
            float4 v = xg4[i];
            xs_T[(4 * c4 + 0) * XT + r] = v.x;
            xs_T[(4 * c4 + 1) * XT + r] = v.y;
            xs_T[(4 * c4 + 2) * XT + r] = v.z;
            xs_T[(4 * c4 + 3) * XT + r] = v.w;
        }
    }
    __syncthreads();

    const int colA = 4 * wid;                        // block A start col
    const int colB = 60 - 4 * wid;                   // block B start col
    const int tripA = 4 * wid + 4;                   // k < tripA   (k <= colA+3)
    const int tripB = 64 - 4 * wid;                  // k < tripB   (k <= colB+3)

    const unsigned xtb = (unsigned)__cvta_generic_to_shared(xs_T) + lane * 4;
    const unsigned uAb = (unsigned)__cvta_generic_to_shared(U_s) + colA * 4;
    const unsigned uBb = (unsigned)__cvta_generic_to_shared(U_s) + colB * 4;

    uint64_t a0 = 0, a1 = 0, b0 = 0, b1 = 0;         // Y accs (4+4 cols, f32x2)

    #pragma unroll 4
    for (int k = 0; k < tripA; ++k) {                // block A: k <= 4c+3
        uint64_t u0, u1;
        lds_v2u64(u0, u1, uAb + k * 256);            // uniform 16B: 1 wf
        uint64_t xk2 = splat(lds32(xtb + k * (XT * 4)));   // 32 rows: 1 wf
        fma2(a0, u0, xk2);
        fma2(a1, u1, xk2);
    }
    #pragma unroll 4
    for (int k = 0; k < tripB; ++k) {                // block B: k <= 63-4c
        uint64_t u0, u1;
        lds_v2u64(u0, u1, uBb + k * 256);
        uint64_t xk2 = splat(lds32(xtb + k * (XT * 4)));
        fma2(b0, u0, xk2);
        fma2(b1, u1, xk2);
    }

    // --- Partial out: dot this warp's 8 Y columns with x[row][col]
    float p = 0.0f;
    {
        uint32_t lo, hi;
        #pragma unroll
        for (int i = 0; i < 2; ++i) {
            uint64_t ya = i ? a1 : a0, yb = i ? b1 : b0;
            asm("mov.b64 {%0,%1}, %2;" : "=r"(lo), "=r"(hi) : "l"(ya));
            p = fmaf(__uint_as_float(lo), lds32(xtb + (colA + 2 * i) * (XT * 4)), p);
            p = fmaf(__uint_as_float(hi), lds32(xtb + (colA + 2 * i + 1) * (XT * 4)), p);
            asm("mov.b64 {%0,%1}, %2;" : "=r"(lo), "=r"(hi) : "l"(yb));
            p = fmaf(__uint_as_float(lo), lds32(xtb + (colB + 2 * i) * (XT * 4)), p);
            p = fmaf(__uint_as_float(hi), lds32(xtb + (colB + 2 * i + 1) * (XT * 4)), p);
        }
    }
    part[wid][lane] = p;
    __syncthreads();

    // --- Warp 0 combines the 8 column-pair partials per row
    if (wid == 0) {
        float s = part[0][lane];
        #pragma unroll
        for (int w = 1; w < 8; ++w) s += part[w][lane];
        out[row0 + lane] = s + __ldg(bias);
    }
}

extern "C" void kernel_launch(void* const* d_in, const int* in_sizes, int n_in,
                              void* d_out, int out_size) {
    const float* x = (const float*)d_in[0];   // (16384, 64) f32
    const float* W = (const float*)d_in[1];   // (2145,)  f32 (first 2080 used)
    const float* b = (const float*)d_in[2];   // (1,)     f32
    float*     out = (float*)d_out;           // (16384,) f32

    const int blocks = out_size / 32;         // 512 CTAs x 256 threads
    honu_kernel<<<blocks, THREADS>>>(x, W, b, out);
}